// round 12
// baseline (speedup 1.0000x reference)
#include <cuda_runtime.h>
#include <cstdint>

// DeepProbLogAdditionReasoner: per-row conv of two length-10 pdfs -> 19 bins, normalized.
// Round-12: R4 champion structure with descriptor-less TMA bulk LOADS.
//   - inputs: two cp.async.bulk (10240B each) issued by tid0 + mbarrier wait
//     -> input request stream generated by the TMA engine, zero warp issue cost
//   - per-row 10x10 FMA conv + normalize in registers
//   - output restaged into the same smem buffer -> single 19456B bulk store
//   - TPB=256, smem ~20.5KB, __launch_bounds__(256,8): 8 CTAs/SM (warp cap)

#define TPB 256
#define IN_BYTES  (TPB * 10 * 4)   // 10240 bytes per input array per block
#define OUT_BYTES (TPB * 19 * 4)   // 19456 bytes output tile per block

__device__ __forceinline__ uint32_t smem_u32(const void* p) {
    uint32_t a;
    asm("{ .reg .u64 t; cvta.to.shared.u64 t, %1; cvt.u32.u64 %0, t; }"
        : "=r"(a) : "l"(p));
    return a;
}

__global__ __launch_bounds__(TPB, 8) void dpl_add_kernel(
    const float* __restrict__ p1,
    const float* __restrict__ p2,
    float* __restrict__ out,
    int B)
{
    // [0 .. TPB*10) = p1 rows, [TPB*10 .. TPB*20) = p2 rows (linear pitch 10)
    // phase 3 reuses [0 .. TPB*19) for the output tile (stride 19)
    __shared__ float sm[TPB * 20];
    __shared__ __align__(8) unsigned long long mbar;

    const int tid = threadIdx.x;
    const long long base = (long long)blockIdx.x * TPB;
    const int rows = (B - base < TPB) ? (int)(B - base) : TPB;
    const bool full = (rows == TPB);

    // ---- Phase 1: TMA bulk loads global -> smem ----
    if (full) {
        const uint32_t mb = smem_u32(&mbar);
        const uint32_t sb = smem_u32(sm);
        if (tid == 0) {
            asm volatile("mbarrier.init.shared.b64 [%0], 1;" :: "r"(mb) : "memory");
            asm volatile("fence.proxy.async.shared::cta;" ::: "memory");
        }
        __syncthreads();   // mbarrier initialized before any wait / TMA completion
        if (tid == 0) {
            asm volatile("mbarrier.arrive.expect_tx.shared.b64 _, [%0], %1;"
                         :: "r"(mb), "r"((uint32_t)(2 * IN_BYTES)) : "memory");
            const float* g1 = p1 + base * 10;
            const float* g2 = p2 + base * 10;
            asm volatile(
                "cp.async.bulk.shared::cta.global.mbarrier::complete_tx::bytes "
                "[%0], [%1], %2, [%3];"
                :: "r"(sb), "l"(g1), "r"((uint32_t)IN_BYTES), "r"(mb) : "memory");
            asm volatile(
                "cp.async.bulk.shared::cta.global.mbarrier::complete_tx::bytes "
                "[%0], [%1], %2, [%3];"
                :: "r"(sb + IN_BYTES), "l"(g2), "r"((uint32_t)IN_BYTES), "r"(mb)
                : "memory");
        }
        // all threads wait for both bulk loads (phase 0)
        {
            uint32_t done;
            asm volatile(
                "{\n\t.reg .pred p;\n\t"
                "mbarrier.try_wait.parity.acquire.cta.shared::cta.b64 p, [%1], 0;\n\t"
                "selp.b32 %0, 1, 0, p;\n\t}"
                : "=r"(done) : "r"(mb) : "memory");
            if (!done) {
                asm volatile(
                    "{\n\t.reg .pred P1;\n\t"
                    "W%=:\n\t"
                    "mbarrier.try_wait.parity.acquire.cta.shared::cta.b64 P1, [%0], 0, 0x989680;\n\t"
                    "@P1 bra.uni D%=;\n\t"
                    "bra.uni W%=;\n\t"
                    "D%=:\n\t}"
                    :: "r"(mb) : "memory");
            }
        }
    } else {
        const float* g1 = p1 + base * 10;
        const float* g2 = p2 + base * 10;
        const int nElems = rows * 10;
        for (int i = tid; i < nElems; i += TPB) {
            sm[i]            = g1[i];
            sm[TPB * 10 + i] = g2[i];
        }
        __syncthreads();
    }

    // ---- Phase 2: per-row convolution + normalize in registers ----
    float r[19];
    if (tid < rows) {
        float a[10], b[10];
        #pragma unroll
        for (int i = 0; i < 10; i++) {
            a[i] = sm[tid * 10 + i];
            b[i] = sm[TPB * 10 + tid * 10 + i];
        }
        #pragma unroll
        for (int k = 0; k < 19; k++) r[k] = 0.0f;
        #pragma unroll
        for (int i = 0; i < 10; i++) {
            #pragma unroll
            for (int j = 0; j < 10; j++) {
                r[i + j] = fmaf(a[i], b[j], r[i + j]);
            }
        }
        float s = 0.0f;
        #pragma unroll
        for (int k = 0; k < 19; k++) s += r[k];
        float inv = 1.0f / (s + 1e-9f);
        #pragma unroll
        for (int k = 0; k < 19; k++) r[k] *= inv;
    }

    __syncthreads();   // inputs consumed; smem reusable for output staging

    // ---- Phase 3: smem stage (stride 19) -> single bulk store ----
    if (tid < rows) {
        #pragma unroll
        for (int k = 0; k < 19; k++) sm[tid * 19 + k] = r[k];
    }
    __syncthreads();

    if (full) {
        if (tid == 0) {
            asm volatile("fence.proxy.async.shared::cta;" ::: "memory");
            float* go = out + base * 19;
            asm volatile(
                "cp.async.bulk.global.shared::cta.bulk_group [%0], [%1], %2;"
                :: "l"(go), "r"(smem_u32(sm)), "r"((uint32_t)OUT_BYTES)
                : "memory");
            asm volatile("cp.async.bulk.commit_group;" ::: "memory");
            asm volatile("cp.async.bulk.wait_group 0;" ::: "memory");
        }
        // other threads retire; CTA smem stays alive until tid 0 finishes
    } else {
        float* go = out + base * 19;
        const int nOut = rows * 19;
        for (int i = tid; i < nOut; i += TPB) go[i] = sm[i];
    }
}

extern "C" void kernel_launch(void* const* d_in, const int* in_sizes, int n_in,
                              void* d_out, int out_size) {
    const float* p1 = (const float*)d_in[0];
    const float* p2 = (const float*)d_in[1];
    float* out = (float*)d_out;
    const int B = in_sizes[0] / 10;
    const int grid = (B + TPB - 1) / TPB;
    dpl_add_kernel<<<grid, TPB>>>(p1, p2, out, B);
}

// round 13
// speedup vs baseline: 1.0191x; 1.0191x over previous
#include <cuda_runtime.h>
#include <cstdint>

// DeepProbLogAdditionReasoner: per-row conv of two length-10 pdfs -> 19 bins, normalized.
// FINAL (champion, R4 structure): measured at the GB300 mixed-R/W HBM ceiling
// (156 MB compulsory traffic @ ~5.33 TB/s sustained ≈ 29.2 us steady-state wall).
//   phase 1: cp.async.cg 16B global->smem staging (register-free, warp-spread MLP)
//   phase 2: per-row 10x10 FMA conv + normalize in registers
//   phase 3: stride-19 smem restage -> single 19456B bulk async store
//   __launch_bounds__(256,8): regs<=32 -> 8 CTAs/SM (warp cap, 64 warps).

#define TPB 256
#define NV4_IN  (TPB * 10 / 4)   // 640 float4 per input array per block
#define OUT_BYTES (TPB * 19 * 4) // 19456 bytes output tile per block

__device__ __forceinline__ uint32_t smem_u32(const void* p) {
    uint32_t a;
    asm("{ .reg .u64 t; cvta.to.shared.u64 t, %1; cvt.u32.u64 %0, t; }"
        : "=r"(a) : "l"(p));
    return a;
}

__device__ __forceinline__ void cp_async16(uint32_t smem_dst, const void* gmem_src) {
    asm volatile("cp.async.cg.shared.global [%0], [%1], 16;"
                 :: "r"(smem_dst), "l"(gmem_src) : "memory");
}

__global__ __launch_bounds__(TPB, 8) void dpl_add_kernel(
    const float* __restrict__ p1,
    const float* __restrict__ p2,
    float* __restrict__ out,
    int B)
{
    // phase 1: [0 .. TPB*10) = p1 rows, [TPB*10 .. TPB*20) = p2 rows (linear pitch 10)
    // phase 3: [0 .. TPB*19) = output rows (stride 19) -- reuses the same buffer
    __shared__ float sm[TPB * 20];
    float4* sm4 = (float4*)sm;

    const int tid = threadIdx.x;
    const long long base = (long long)blockIdx.x * TPB;
    const int rows = (B - base < TPB) ? (int)(B - base) : TPB;
    const bool full = (rows == TPB);

    // ---- Phase 1: async vectorized global -> smem (no register round-trip) ----
    if (full) {
        const float4* g14 = (const float4*)(p1 + base * 10);
        const float4* g24 = (const float4*)(p2 + base * 10);
        const uint32_t s_base = smem_u32(sm4);
        #pragma unroll
        for (int i = tid; i < NV4_IN; i += TPB) {
            cp_async16(s_base + i * 16,            g14 + i);
            cp_async16(s_base + (NV4_IN + i) * 16, g24 + i);
        }
        asm volatile("cp.async.commit_group;" ::: "memory");
        asm volatile("cp.async.wait_group 0;" ::: "memory");
    } else {
        const float* g1 = p1 + base * 10;
        const float* g2 = p2 + base * 10;
        const int nElems = rows * 10;
        for (int i = tid; i < nElems; i += TPB) {
            sm[i]            = g1[i];
            sm[TPB * 10 + i] = g2[i];
        }
    }
    __syncthreads();

    // ---- Phase 2: per-row convolution + normalize in registers ----
    float r[19];
    if (tid < rows) {
        float a[10], b[10];
        #pragma unroll
        for (int i = 0; i < 10; i++) {
            a[i] = sm[tid * 10 + i];
            b[i] = sm[TPB * 10 + tid * 10 + i];
        }
        #pragma unroll
        for (int k = 0; k < 19; k++) r[k] = 0.0f;
        #pragma unroll
        for (int i = 0; i < 10; i++) {
            #pragma unroll
            for (int j = 0; j < 10; j++) {
                r[i + j] = fmaf(a[i], b[j], r[i + j]);
            }
        }
        float s = 0.0f;
        #pragma unroll
        for (int k = 0; k < 19; k++) s += r[k];
        float inv = 1.0f / (s + 1e-9f);
        #pragma unroll
        for (int k = 0; k < 19; k++) r[k] *= inv;
    }

    __syncthreads();   // inputs consumed; smem reusable for output staging

    // ---- Phase 3: smem stage (stride 19, conflict-free) -> bulk async store ----
    if (tid < rows) {
        #pragma unroll
        for (int k = 0; k < 19; k++) sm[tid * 19 + k] = r[k];
    }
    __syncthreads();

    if (full) {
        if (tid == 0) {
            // order generic smem writes before async-proxy read
            asm volatile("fence.proxy.async.shared::cta;" ::: "memory");
            float* go = out + base * 19;
            asm volatile(
                "cp.async.bulk.global.shared::cta.bulk_group [%0], [%1], %2;"
                :: "l"(go), "r"(smem_u32(sm)), "r"((uint32_t)OUT_BYTES)
                : "memory");
            asm volatile("cp.async.bulk.commit_group;" ::: "memory");
            asm volatile("cp.async.bulk.wait_group 0;" ::: "memory");
        }
        // other threads retire; CTA smem stays alive until tid 0 finishes
    } else {
        float* go = out + base * 19;
        const int nOut = rows * 19;
        for (int i = tid; i < nOut; i += TPB) go[i] = sm[i];
    }
}

extern "C" void kernel_launch(void* const* d_in, const int* in_sizes, int n_in,
                              void* d_out, int out_size) {
    const float* p1 = (const float*)d_in[0];
    const float* p2 = (const float*)d_in[1];
    float* out = (float*)d_out;
    const int B = in_sizes[0] / 10;
    const int grid = (B + TPB - 1) / TPB;
    dpl_add_kernel<<<grid, TPB>>>(p1, p2, out, B);
}

// round 14
// speedup vs baseline: 1.0571x; 1.0374x over previous
#include <cuda_runtime.h>
#include <cstdint>

// DeepProbLogAdditionReasoner: per-row conv of two length-10 pdfs -> 19 bins, normalized.
// FINAL champion (R4 structure) + wait_group.read tail release.
// Measured at the GB300 mixed-R/W HBM ceiling: 156 MB compulsory traffic at
// ~5.3 TB/s sustained ≈ 29 us steady-state wall.
//   phase 1: cp.async.cg 16B global->smem staging (register-free, warp-spread MLP)
//   phase 2: per-row 10x10 FMA conv + normalize in registers
//   phase 3: stride-19 smem restage -> single 19456B bulk async store;
//            CTA retires as soon as the bulk engine has READ smem
//            (wait_group.read), the GMEM write drains after retirement.
//   __launch_bounds__(256,8): regs<=32 -> 8 CTAs/SM (warp cap, 64 warps).

#define TPB 256
#define NV4_IN  (TPB * 10 / 4)   // 640 float4 per input array per block
#define OUT_BYTES (TPB * 19 * 4) // 19456 bytes output tile per block

__device__ __forceinline__ uint32_t smem_u32(const void* p) {
    uint32_t a;
    asm("{ .reg .u64 t; cvta.to.shared.u64 t, %1; cvt.u32.u64 %0, t; }"
        : "=r"(a) : "l"(p));
    return a;
}

__device__ __forceinline__ void cp_async16(uint32_t smem_dst, const void* gmem_src) {
    asm volatile("cp.async.cg.shared.global [%0], [%1], 16;"
                 :: "r"(smem_dst), "l"(gmem_src) : "memory");
}

__global__ __launch_bounds__(TPB, 8) void dpl_add_kernel(
    const float* __restrict__ p1,
    const float* __restrict__ p2,
    float* __restrict__ out,
    int B)
{
    // phase 1: [0 .. TPB*10) = p1 rows, [TPB*10 .. TPB*20) = p2 rows (linear pitch 10)
    // phase 3: [0 .. TPB*19) = output rows (stride 19) -- reuses the same buffer
    __shared__ float sm[TPB * 20];
    float4* sm4 = (float4*)sm;

    const int tid = threadIdx.x;
    const long long base = (long long)blockIdx.x * TPB;
    const int rows = (B - base < TPB) ? (int)(B - base) : TPB;
    const bool full = (rows == TPB);

    // ---- Phase 1: async vectorized global -> smem (no register round-trip) ----
    if (full) {
        const float4* g14 = (const float4*)(p1 + base * 10);
        const float4* g24 = (const float4*)(p2 + base * 10);
        const uint32_t s_base = smem_u32(sm4);
        #pragma unroll
        for (int i = tid; i < NV4_IN; i += TPB) {
            cp_async16(s_base + i * 16,            g14 + i);
            cp_async16(s_base + (NV4_IN + i) * 16, g24 + i);
        }
        asm volatile("cp.async.commit_group;" ::: "memory");
        asm volatile("cp.async.wait_group 0;" ::: "memory");
    } else {
        const float* g1 = p1 + base * 10;
        const float* g2 = p2 + base * 10;
        const int nElems = rows * 10;
        for (int i = tid; i < nElems; i += TPB) {
            sm[i]            = g1[i];
            sm[TPB * 10 + i] = g2[i];
        }
    }
    __syncthreads();

    // ---- Phase 2: per-row convolution + normalize in registers ----
    float r[19];
    if (tid < rows) {
        float a[10], b[10];
        #pragma unroll
        for (int i = 0; i < 10; i++) {
            a[i] = sm[tid * 10 + i];
            b[i] = sm[TPB * 10 + tid * 10 + i];
        }
        #pragma unroll
        for (int k = 0; k < 19; k++) r[k] = 0.0f;
        #pragma unroll
        for (int i = 0; i < 10; i++) {
            #pragma unroll
            for (int j = 0; j < 10; j++) {
                r[i + j] = fmaf(a[i], b[j], r[i + j]);
            }
        }
        float s = 0.0f;
        #pragma unroll
        for (int k = 0; k < 19; k++) s += r[k];
        float inv = 1.0f / (s + 1e-9f);
        #pragma unroll
        for (int k = 0; k < 19; k++) r[k] *= inv;
    }

    __syncthreads();   // inputs consumed; smem reusable for output staging

    // ---- Phase 3: smem stage (stride 19, conflict-free) -> bulk async store ----
    if (tid < rows) {
        #pragma unroll
        for (int k = 0; k < 19; k++) sm[tid * 19 + k] = r[k];
    }
    __syncthreads();

    if (full) {
        if (tid == 0) {
            // order generic smem writes before async-proxy read
            asm volatile("fence.proxy.async.shared::cta;" ::: "memory");
            float* go = out + base * 19;
            asm volatile(
                "cp.async.bulk.global.shared::cta.bulk_group [%0], [%1], %2;"
                :: "l"(go), "r"(smem_u32(sm)), "r"((uint32_t)OUT_BYTES)
                : "memory");
            asm volatile("cp.async.bulk.commit_group;" ::: "memory");
            // wait only for the SMEM READ side of the store: the CTA (and its
            // smem) can be released while the GMEM write drains asynchronously.
            asm volatile("cp.async.bulk.wait_group.read 0;" ::: "memory");
        }
    } else {
        float* go = out + base * 19;
        const int nOut = rows * 19;
        for (int i = tid; i < nOut; i += TPB) go[i] = sm[i];
    }
}

extern "C" void kernel_launch(void* const* d_in, const int* in_sizes, int n_in,
                              void* d_out, int out_size) {
    const float* p1 = (const float*)d_in[0];
    const float* p2 = (const float*)d_in[1];
    float* out = (float*)d_out;
    const int B = in_sizes[0] / 10;
    const int grid = (B + TPB - 1) / TPB;
    dpl_add_kernel<<<grid, TPB>>>(p1, p2, out, B);
}